// round 6
// baseline (speedup 1.0000x reference)
#include <cuda_runtime.h>
#include <stdint.h>

// ---------------- problem constants ----------------
// SPARSE_SHAPE (468,468,1), WINDOW (12,12,1), BATCH 4
// _NX=_NY=40, _NZ=2 ; win_z==0 always ; full_win = 2*compact
// compact win id = b*1600 + wx*40 + wy  in [0, 6400)
#define NWc   6400
#define CAP   512               // max voxels per window (uniform data: ~49 mean)
#define MAXN  327680
#define FULLM 0xFFFFFFFFu

// ---------------- static scratch (no allocations allowed) -------------------
__device__ int           g_cnt0[NWc];
__device__ int           g_cnt1[NWc];
__device__ int           g_bkt0[NWc * CAP];   // voxel indices per window, round 0
__device__ int           g_bkt1[NWc * CAP];   // round 1
__device__ int           g_winc0[MAXN];
__device__ int           g_winc1[MAXN];
__device__ int           g_inner0[MAXN];
__device__ int           g_inner1[MAXN];
__device__ unsigned char g_keep0[MAXN];
__device__ unsigned char g_keepF[MAXN];

__device__ __forceinline__ void lvl_target(int n, int& lvl, int& target) {
    if (n < 16)      { lvl = 0; target = 16; }
    else if (n < 32) { lvl = 1; target = 32; }
    else if (n < 64) { lvl = 2; target = 64; }
    else             { lvl = 3; target = 144; }
}

// ---------------- phase 0: zero the 2x6400 window counters ------------------
__global__ void k_zerocnt() {
    int i = blockIdx.x * blockDim.x + threadIdx.x;
    if (i < NWc) { g_cnt0[i] = 0; g_cnt1[i] = 0; }
}

// ---------------- phase 1: window ids + bucket scatter (round 0) ------------
__global__ void k_scatter0(const int* __restrict__ coords, int N) {
    for (int i = blockIdx.x * blockDim.x + threadIdx.x; i < N;
         i += gridDim.x * blockDim.x) {
        int4 cc = ((const int4*)coords)[i];          // (b,z,y,x)
        int b = cc.x, y = cc.z, x = cc.w;
        int w0 = b * 1600 + ((x + 12) / 12) * 40 + ((y + 12) / 12);
        int w1 = b * 1600 + ((x + 6)  / 12) * 40 + ((y + 6)  / 12);
        g_winc0[i] = w0;
        g_winc1[i] = w1;
        int pos = atomicAdd(&g_cnt0[w0], 1);
        if (pos < CAP) g_bkt0[w0 * CAP + pos] = i;
    }
}

// ---------------- phase 2: rank round 0 + inline scatter to round-1 buckets -
// rank of element = number of bucket entries with smaller voxel index (stable).
__global__ void __launch_bounds__(128)
k_wrank0s1() {
    __shared__ int s[CAP];
    int w = blockIdx.x;
    int n = g_cnt0[w];
    if (n > CAP) n = CAP;
    for (int t = threadIdx.x; t < n; t += 128) s[t] = g_bkt0[w * CAP + t];
    __syncthreads();
    int lvl, target; lvl_target(n, lvl, target);
    for (int e = threadIdx.x; e < n; e += 128) {
        int my = s[e];
        int r = 0;
        for (int j = 0; j < n; j++) r += (s[j] < my);
        g_inner0[my] = r;
        int kp = (r < target);
        g_keep0[my] = kp;
        if (kp) {
            int w1 = g_winc1[my];
            int pos = atomicAdd(&g_cnt1[w1], 1);
            if (pos < CAP) g_bkt1[w1 * CAP + pos] = my;
        } else {
            g_inner1[my] = -1;
            g_keepF[my]  = 0;
        }
    }
}

// ---------------- phase 3: per-window stable rank (round 1) -----------------
__global__ void __launch_bounds__(128)
k_wrank1() {
    __shared__ int s[CAP];
    int w = blockIdx.x;
    int n = g_cnt1[w];
    if (n > CAP) n = CAP;
    for (int t = threadIdx.x; t < n; t += 128) s[t] = g_bkt1[w * CAP + t];
    __syncthreads();
    int lvl, target; lvl_target(n, lvl, target);
    for (int e = threadIdx.x; e < n; e += 128) {
        int my = s[e];
        int r = 0;
        for (int j = 0; j < n; j++) r += (s[j] < my);
        g_inner1[my] = r;
        g_keepF[my]  = (r < target) ? 1 : 0;
    }
}

// ---------------- independent branch: positional embeddings (coords only) ---
__global__ void __launch_bounds__(128)
k_pe(const int* __restrict__ coords, float* __restrict__ out, int N, int C,
     size_t off_pe0, size_t off_pe1) {
    int cidx = threadIdx.x;           // 0..C-1 (C=128)
    int half = C >> 1;                // 64
    bool isy = cidx >= half;
    int j = (isy ? (cidx - half) : cidx) >> 1;        // freq index 0..31
    bool iscos = (cidx & 1);
    // 1/inv_freq = 10000^(-(2j)/(C/2)) = 2^(-j * 4*log2(1e4)/C)
    float rec = exp2f(-(float)j * (13.28771237954944987f * 4.0f / (float)C));

    for (int i = blockIdx.x; i < N; i += gridDim.x) {
        int x = __ldg(&coords[i * 4 + 3]);
        int y = __ldg(&coords[i * 4 + 2]);
        int v = isy ? y : x;
        float v0 = (float)(v % 12) - 6.0f;            // unshifted in-window coord - w/2
        float v1 = (float)((v + 6) % 12) - 6.0f;      // shifted
        float a0 = v0 * rec, a1 = v1 * rec;
        size_t row = (size_t)i * C + cidx;
        out[off_pe0 + row] = iscos ? __cosf(a0) : __sinf(a0);
        out[off_pe1 + row] = iscos ? __cosf(a1) : __sinf(a1);
    }
}

// ---------------- final: masked features + all scalar vectors --------------
__global__ void __launch_bounds__(128)
k_featvec(const float* __restrict__ feat, float* __restrict__ out, int N, int C,
          size_t off_keep, size_t off_w0, size_t off_w1,
          size_t off_dl0, size_t off_dl1, size_t off_i0, size_t off_i1) {
    int cidx = threadIdx.x;
    for (int i = blockIdx.x; i < N; i += gridDim.x) {
        float kf = g_keepF[i] ? 1.0f : 0.0f;
        size_t row = (size_t)i * C + cidx;
        out[row] = feat[row] * kf;
        if (cidx < 7) {
            float v;
            switch (cidx) {
                case 0: v = kf; break;
                case 1: v = (float)(2 * g_winc0[i]); break;
                case 2: v = (float)(2 * g_winc1[i]); break;
                case 3: { int l, t; lvl_target(g_cnt0[g_winc0[i]], l, t);
                          v = (float)l; } break;
                case 4: { v = -1.0f;
                          if (g_keep0[i]) { int l, t; lvl_target(g_cnt1[g_winc1[i]], l, t);
                                            v = (float)l; } } break;
                case 5: v = (float)g_inner0[i]; break;
                default: v = (float)g_inner1[i]; break;
            }
            size_t base = (cidx == 0) ? off_keep : (cidx == 1) ? off_w0 :
                          (cidx == 2) ? off_w1  : (cidx == 3) ? off_dl0 :
                          (cidx == 4) ? off_dl1 : (cidx == 5) ? off_i0 : off_i1;
            out[base + i] = v;
        }
    }
}

// ---------------- launch ----------------
extern "C" void kernel_launch(void* const* d_in, const int* in_sizes, int n_in,
                              void* d_out, int out_size) {
    const float* feat   = (const float*)d_in[0];
    const int*   coords = (const int*)d_in[1];
    int N = in_sizes[1] / 4;
    int C = in_sizes[0] / N;          // 128
    if (N > MAXN) N = MAXN;           // safety (setup gives exactly 300000)

    float* out = (float*)d_out;
    size_t Ns = (size_t)N, Cs = (size_t)C;
    size_t off = Ns * Cs;             // feat at 0
    size_t off_keep = off; off += Ns;
    size_t off_w0   = off; off += Ns;
    size_t off_w1   = off; off += Ns;
    size_t off_dl0  = off; off += Ns;
    size_t off_dl1  = off; off += Ns;
    size_t off_i0   = off; off += Ns;
    size_t off_i1   = off; off += Ns;
    size_t off_pe0  = off; off += Ns * Cs;
    size_t off_pe1  = off;

    // Fork a second stream for the coords-only PE branch so the latency-bound
    // rank chain overlaps the bandwidth-bound PE writes. Event fork/join keeps
    // this graph-capturable (branches become parallel graph nodes).
    cudaStream_t s2;
    cudaStreamCreateWithFlags(&s2, cudaStreamNonBlocking);
    cudaEvent_t eFork, eJoin;
    cudaEventCreateWithFlags(&eFork, cudaEventDisableTiming);
    cudaEventCreateWithFlags(&eJoin, cudaEventDisableTiming);

    cudaEventRecord(eFork, 0);              // on the (captured) default stream
    cudaStreamWaitEvent(s2, eFork, 0);      // fork

    // branch B: positional embeddings (independent of keep/rank)
    k_pe<<<2368, 128, 0, s2>>>(coords, out, N, C, off_pe0, off_pe1);

    // branch A: rank pipeline + dependent outputs (default stream)
    k_zerocnt<<<(NWc + 255) / 256, 256>>>();
    k_scatter0<<<592, 256>>>(coords, N);
    k_wrank0s1<<<NWc, 128>>>();
    k_wrank1<<<NWc, 128>>>();
    k_featvec<<<2368, 128>>>(feat, out, N, C, off_keep, off_w0, off_w1,
                             off_dl0, off_dl1, off_i0, off_i1);

    cudaEventRecord(eJoin, s2);
    cudaStreamWaitEvent(0, eJoin, 0);       // join back to default stream
    // Note: s2/events are intentionally not destroyed here — destroying a
    // stream participating in an active capture invalidates the capture.
    // kernel_launch is invoked only a handful of times (correctness + capture).
}

// round 7
// speedup vs baseline: 1.0847x; 1.0847x over previous
#include <cuda_runtime.h>
#include <stdint.h>

// ---------------- problem constants ----------------
// SPARSE_SHAPE (468,468,1), WINDOW (12,12,1), BATCH 4
// _NX=_NY=40, _NZ=2 ; win_z==0 always ; full_win = 2*compact
// compact win id = b*1600 + wx*40 + wy  in [0, 6400)
#define NWc   6400
#define CAP   512               // max voxels per window (uniform data: ~49 mean)
#define MAXN  327680
#define FULLM 0xFFFFFFFFu

// ---------------- static scratch (no allocations allowed) -------------------
__device__ int           g_cnt0[NWc];
__device__ int           g_cnt1[NWc];
__device__ int           g_bkt0[NWc * CAP];   // voxel indices per window, round 0
__device__ int           g_bkt1[NWc * CAP];   // round 1
__device__ int           g_winc0[MAXN];
__device__ int           g_winc1[MAXN];
__device__ int           g_inner0[MAXN];
__device__ int           g_inner1[MAXN];
__device__ unsigned char g_keep0[MAXN];
__device__ unsigned char g_keepF[MAXN];

__device__ __forceinline__ void lvl_target(int n, int& lvl, int& target) {
    if (n < 16)      { lvl = 0; target = 16; }
    else if (n < 32) { lvl = 1; target = 32; }
    else if (n < 64) { lvl = 2; target = 64; }
    else             { lvl = 3; target = 144; }
}

// ---------------- phase 0: zero the 2x6400 window counters ------------------
__global__ void k_zerocnt() {
    int i = blockIdx.x * blockDim.x + threadIdx.x;
    if (i < NWc) { g_cnt0[i] = 0; g_cnt1[i] = 0; }
}

// ---------------- phase 1: window ids + bucket scatter (round 0) ------------
__global__ void k_scatter0(const int* __restrict__ coords, int N) {
    for (int i = blockIdx.x * blockDim.x + threadIdx.x; i < N;
         i += gridDim.x * blockDim.x) {
        int4 cc = ((const int4*)coords)[i];          // (b,z,y,x)
        int b = cc.x, y = cc.z, x = cc.w;
        int w0 = b * 1600 + ((x + 12) / 12) * 40 + ((y + 12) / 12);
        int w1 = b * 1600 + ((x + 6)  / 12) * 40 + ((y + 6)  / 12);
        g_winc0[i] = w0;
        g_winc1[i] = w1;
        int pos = atomicAdd(&g_cnt0[w0], 1);
        if (pos < CAP) g_bkt0[w0 * CAP + pos] = i;
    }
}

// ---------------- phase 2: rank round 0 + inline scatter to round-1 buckets -
// rank of element = number of bucket entries with smaller voxel index (stable).
__global__ void __launch_bounds__(128)
k_wrank0s1() {
    __shared__ int s[CAP];
    int w = blockIdx.x;
    int n = g_cnt0[w];
    if (n > CAP) n = CAP;
    for (int t = threadIdx.x; t < n; t += 128) s[t] = g_bkt0[w * CAP + t];
    __syncthreads();
    int lvl, target; lvl_target(n, lvl, target);
    for (int e = threadIdx.x; e < n; e += 128) {
        int my = s[e];
        int r = 0;
        for (int j = 0; j < n; j++) r += (s[j] < my);
        g_inner0[my] = r;
        int kp = (r < target);
        g_keep0[my] = kp;
        if (kp) {
            int w1 = g_winc1[my];
            int pos = atomicAdd(&g_cnt1[w1], 1);
            if (pos < CAP) g_bkt1[w1 * CAP + pos] = my;
        } else {
            g_inner1[my] = -1;
            g_keepF[my]  = 0;
        }
    }
}

// ---------------- phase 3: per-window stable rank (round 1) -----------------
__global__ void __launch_bounds__(128)
k_wrank1() {
    __shared__ int s[CAP];
    int w = blockIdx.x;
    int n = g_cnt1[w];
    if (n > CAP) n = CAP;
    for (int t = threadIdx.x; t < n; t += 128) s[t] = g_bkt1[w * CAP + t];
    __syncthreads();
    int lvl, target; lvl_target(n, lvl, target);
    for (int e = threadIdx.x; e < n; e += 128) {
        int my = s[e];
        int r = 0;
        for (int j = 0; j < n; j++) r += (s[j] < my);
        g_inner1[my] = r;
        g_keepF[my]  = (r < target) ? 1 : 0;
    }
}

// ---------------- phase 4: ALL outputs in one bandwidth-bound pass ----------
// 128 threads/block = one feature channel each; block-strided over rows.
// Writes feat_kept, pe0, pe1 (coalesced 512B rows) and, from lanes 0..6,
// the seven scalar vectors.
__global__ void __launch_bounds__(128)
k_outall(const float* __restrict__ feat, const int* __restrict__ coords,
         float* __restrict__ out, int N, int C,
         size_t off_keep, size_t off_w0, size_t off_w1,
         size_t off_dl0, size_t off_dl1, size_t off_i0, size_t off_i1,
         size_t off_pe0, size_t off_pe1) {
    int cidx = threadIdx.x;           // 0..C-1 (C=128)
    int half = C >> 1;                // 64
    bool isy = cidx >= half;
    int j = (isy ? (cidx - half) : cidx) >> 1;        // freq index 0..31
    bool iscos = (cidx & 1);
    // 1/inv_freq = 10000^(-(2j)/(C/2)) = 2^(-j * 4*log2(1e4)/C)
    float rec = exp2f(-(float)j * (13.28771237954944987f * 4.0f / (float)C));

    for (int i = blockIdx.x; i < N; i += gridDim.x) {
        int x = __ldg(&coords[i * 4 + 3]);
        int y = __ldg(&coords[i * 4 + 2]);
        float kf = g_keepF[i] ? 1.0f : 0.0f;
        size_t row = (size_t)i * C + cidx;
        out[row] = feat[row] * kf;

        int v = isy ? y : x;
        float v0 = (float)(v % 12) - 6.0f;            // unshifted in-window coord - w/2
        float v1 = (float)((v + 6) % 12) - 6.0f;      // shifted
        float a0 = v0 * rec, a1 = v1 * rec;
        out[off_pe0 + row] = iscos ? __cosf(a0) : __sinf(a0);
        out[off_pe1 + row] = iscos ? __cosf(a1) : __sinf(a1);

        if (cidx < 7) {
            float s;
            size_t base;
            switch (cidx) {
                case 0: s = kf;                          base = off_keep; break;
                case 1: s = (float)(2 * g_winc0[i]);     base = off_w0;   break;
                case 2: s = (float)(2 * g_winc1[i]);     base = off_w1;   break;
                case 3: { int l, t; lvl_target(g_cnt0[g_winc0[i]], l, t);
                          s = (float)l;                  base = off_dl0; } break;
                case 4: { s = -1.0f;
                          if (g_keep0[i]) { int l, t;
                              lvl_target(g_cnt1[g_winc1[i]], l, t); s = (float)l; }
                          base = off_dl1; } break;
                case 5: s = (float)g_inner0[i];          base = off_i0;   break;
                default: s = (float)g_inner1[i];         base = off_i1;   break;
            }
            out[base + i] = s;
        }
    }
}

// ---------------- launch ----------------
extern "C" void kernel_launch(void* const* d_in, const int* in_sizes, int n_in,
                              void* d_out, int out_size) {
    const float* feat   = (const float*)d_in[0];
    const int*   coords = (const int*)d_in[1];
    int N = in_sizes[1] / 4;
    int C = in_sizes[0] / N;          // 128
    if (N > MAXN) N = MAXN;           // safety (setup gives exactly 300000)

    float* out = (float*)d_out;
    size_t Ns = (size_t)N, Cs = (size_t)C;
    size_t off = Ns * Cs;             // feat at 0
    size_t off_keep = off; off += Ns;
    size_t off_w0   = off; off += Ns;
    size_t off_w1   = off; off += Ns;
    size_t off_dl0  = off; off += Ns;
    size_t off_dl1  = off; off += Ns;
    size_t off_i0   = off; off += Ns;
    size_t off_i1   = off; off += Ns;
    size_t off_pe0  = off; off += Ns * Cs;
    size_t off_pe1  = off;

    k_zerocnt<<<(NWc + 255) / 256, 256>>>();
    k_scatter0<<<592, 256>>>(coords, N);
    k_wrank0s1<<<NWc, 128>>>();
    k_wrank1<<<NWc, 128>>>();
    k_outall<<<2368, 128>>>(feat, coords, out, N, C,
                            off_keep, off_w0, off_w1,
                            off_dl0, off_dl1, off_i0, off_i1,
                            off_pe0, off_pe1);
}

// round 8
// speedup vs baseline: 3.0241x; 2.7879x over previous
#include <cuda_runtime.h>
#include <stdint.h>

// ---------------- problem constants ----------------
// SPARSE_SHAPE (468,468,1), WINDOW (12,12,1), BATCH 4
// _NX=_NY=40, _NZ=2 ; win_z==0 always ; full_win = 2*compact
// compact win id = b*1600 + wx*40 + wy  in [0, 6400)
#define NWc   6400
#define CAP   512               // max voxels per window (uniform data: ~49 mean)
#define MAXN  327680
#define FULLM 0xFFFFFFFFu

// ---------------- static scratch (no allocations allowed) -------------------
__device__ int           g_cnt0[NWc];
__device__ int           g_cnt1[NWc];
__device__ int           g_bkt0[NWc * CAP];   // voxel indices per window, round 0
__device__ int           g_bkt1[NWc * CAP];   // round 1
__device__ int           g_winc0[MAXN];
__device__ int           g_winc1[MAXN];
__device__ int           g_inner0[MAXN];
__device__ int           g_inner1[MAXN];
__device__ unsigned char g_keep0[MAXN];
__device__ unsigned char g_keepF[MAXN];

__device__ __forceinline__ void lvl_target(int n, int& lvl, int& target) {
    if (n < 16)      { lvl = 0; target = 16; }
    else if (n < 32) { lvl = 1; target = 32; }
    else if (n < 64) { lvl = 2; target = 64; }
    else             { lvl = 3; target = 144; }
}

// ---------------- phase 0: zero the 2x6400 window counters ------------------
__global__ void k_zerocnt() {
    int i = blockIdx.x * blockDim.x + threadIdx.x;
    if (i < NWc) { g_cnt0[i] = 0; g_cnt1[i] = 0; }
}

// ---------------- phase 1: window ids + bucket scatter (round 0) ------------
__global__ void k_scatter0(const int* __restrict__ coords, int N) {
    for (int i = blockIdx.x * blockDim.x + threadIdx.x; i < N;
         i += gridDim.x * blockDim.x) {
        int4 cc = ((const int4*)coords)[i];          // (b,z,y,x)
        int b = cc.x, y = cc.z, x = cc.w;
        int w0 = b * 1600 + ((x + 12) / 12) * 40 + ((y + 12) / 12);
        int w1 = b * 1600 + ((x + 6)  / 12) * 40 + ((y + 6)  / 12);
        g_winc0[i] = w0;
        g_winc1[i] = w1;
        int pos = atomicAdd(&g_cnt0[w0], 1);
        if (pos < CAP) g_bkt0[w0 * CAP + pos] = i;
    }
}

// ---------------- phase 2: rank round 0 + inline scatter to round-1 buckets -
// rank of element = number of bucket entries with smaller voxel index (stable).
__global__ void __launch_bounds__(128)
k_wrank0s1() {
    __shared__ int s[CAP];
    int w = blockIdx.x;
    int n = g_cnt0[w];
    if (n > CAP) n = CAP;
    for (int t = threadIdx.x; t < n; t += 128) s[t] = g_bkt0[w * CAP + t];
    __syncthreads();
    int lvl, target; lvl_target(n, lvl, target);
    for (int e = threadIdx.x; e < n; e += 128) {
        int my = s[e];
        int r = 0;
        for (int j = 0; j < n; j++) r += (s[j] < my);
        g_inner0[my] = r;
        int kp = (r < target);
        g_keep0[my] = kp;
        if (kp) {
            int w1 = g_winc1[my];
            int pos = atomicAdd(&g_cnt1[w1], 1);
            if (pos < CAP) g_bkt1[w1 * CAP + pos] = my;
        } else {
            g_inner1[my] = -1;
            g_keepF[my]  = 0;
        }
    }
}

// ---------------- phase 3: per-window stable rank (round 1) -----------------
__global__ void __launch_bounds__(128)
k_wrank1() {
    __shared__ int s[CAP];
    int w = blockIdx.x;
    int n = g_cnt1[w];
    if (n > CAP) n = CAP;
    for (int t = threadIdx.x; t < n; t += 128) s[t] = g_bkt1[w * CAP + t];
    __syncthreads();
    int lvl, target; lvl_target(n, lvl, target);
    for (int e = threadIdx.x; e < n; e += 128) {
        int my = s[e];
        int r = 0;
        for (int j = 0; j < n; j++) r += (s[j] < my);
        g_inner1[my] = r;
        g_keepF[my]  = (r < target) ? 1 : 0;
    }
}

// ---------------- phase 4a: scalar output vectors (flat, non-divergent) -----
// One thread per voxel: all gathers issue with full TLP. Keep this SEPARATE
// from the row-streaming kernel — fusing it as lane-divergent cases serialized
// dependent gathers inside one warp per block (the R5/R6 4x regression).
__global__ void k_outvec(float* __restrict__ out, int N,
                         size_t off_keep, size_t off_w0, size_t off_w1,
                         size_t off_dl0, size_t off_dl1,
                         size_t off_i0, size_t off_i1) {
    for (int i = blockIdx.x * blockDim.x + threadIdx.x; i < N;
         i += gridDim.x * blockDim.x) {
        int w0 = g_winc0[i], w1 = g_winc1[i];
        out[off_keep + i] = g_keepF[i] ? 1.0f : 0.0f;
        out[off_w0 + i]   = (float)(2 * w0);
        out[off_w1 + i]   = (float)(2 * w1);
        int l0, t0; lvl_target(g_cnt0[w0], l0, t0);
        out[off_dl0 + i] = (float)l0;
        float dl1 = -1.0f;
        if (g_keep0[i]) {
            int l1, t1; lvl_target(g_cnt1[w1], l1, t1);
            dl1 = (float)l1;
        }
        out[off_dl1 + i] = dl1;
        out[off_i0 + i] = (float)g_inner0[i];
        out[off_i1 + i] = (float)g_inner1[i];
    }
}

// ---------------- phase 4b: masked features + positional embeddings ---------
// thread = feature channel; uniform control flow; coalesced 512B row writes.
__global__ void __launch_bounds__(128)
k_outfeat(const float* __restrict__ feat, const int* __restrict__ coords,
          float* __restrict__ out, int N, int C,
          size_t off_pe0, size_t off_pe1) {
    int cidx = threadIdx.x;           // 0..C-1 (C=128)
    int half = C >> 1;                // 64
    bool isy = cidx >= half;
    int j = (isy ? (cidx - half) : cidx) >> 1;        // freq index 0..31
    bool iscos = (cidx & 1);
    // 1/inv_freq = 10000^(-(2j)/(C/2)) = 2^(-j * 4*log2(1e4)/C)
    float rec = exp2f(-(float)j * (13.28771237954944987f * 4.0f / (float)C));

    for (int i = blockIdx.x; i < N; i += gridDim.x) {
        int x = __ldg(&coords[i * 4 + 3]);
        int y = __ldg(&coords[i * 4 + 2]);
        float kf = g_keepF[i] ? 1.0f : 0.0f;
        size_t row = (size_t)i * C + cidx;
        out[row] = feat[row] * kf;

        int v = isy ? y : x;
        float v0 = (float)(v % 12) - 6.0f;            // unshifted in-window coord - w/2
        float v1 = (float)((v + 6) % 12) - 6.0f;      // shifted
        float a0 = v0 * rec, a1 = v1 * rec;
        out[off_pe0 + row] = iscos ? __cosf(a0) : __sinf(a0);
        out[off_pe1 + row] = iscos ? __cosf(a1) : __sinf(a1);
    }
}

// ---------------- launch ----------------
extern "C" void kernel_launch(void* const* d_in, const int* in_sizes, int n_in,
                              void* d_out, int out_size) {
    const float* feat   = (const float*)d_in[0];
    const int*   coords = (const int*)d_in[1];
    int N = in_sizes[1] / 4;
    int C = in_sizes[0] / N;          // 128
    if (N > MAXN) N = MAXN;           // safety (setup gives exactly 300000)

    float* out = (float*)d_out;
    size_t Ns = (size_t)N, Cs = (size_t)C;
    size_t off = Ns * Cs;             // feat at 0
    size_t off_keep = off; off += Ns;
    size_t off_w0   = off; off += Ns;
    size_t off_w1   = off; off += Ns;
    size_t off_dl0  = off; off += Ns;
    size_t off_dl1  = off; off += Ns;
    size_t off_i0   = off; off += Ns;
    size_t off_i1   = off; off += Ns;
    size_t off_pe0  = off; off += Ns * Cs;
    size_t off_pe1  = off;

    k_zerocnt<<<(NWc + 255) / 256, 256>>>();
    k_scatter0<<<592, 256>>>(coords, N);
    k_wrank0s1<<<NWc, 128>>>();
    k_wrank1<<<NWc, 128>>>();
    k_outvec<<<512, 256>>>(out, N, off_keep, off_w0, off_w1,
                           off_dl0, off_dl1, off_i0, off_i1);
    k_outfeat<<<2368, 128>>>(feat, coords, out, N, C, off_pe0, off_pe1);
}